// round 12
// baseline (speedup 1.0000x reference)
#include <cuda_runtime.h>
#include <cuda_bf16.h>
#include <cstdint>

#define HID  200
#define DD   8
#define SB   8            // samples per block
#define NCOL 4            // columns per thread
#define NG   50           // column groups (50 * 4 = 200)
#define NTH  224          // 50 groups * 4 sample-pairs = 200 active (+24 idle)
#define NW   7
#define SPS  20           // floats per sample-pair record (18 used: 8 dirs x2 + primal x2)
#define PADK 84           // floats per k row: 4*SPS=80 +4 pad
#define EPSV 0.1f
#define DSMEM (HID * PADK * 4)   // 67200 bytes dynamic

// Column-duplicated weights (device scratch): Wd[k][2c] = Wd[k][2c+1] = W[k][c]
__device__ float g_W1d [HID * 2 * HID];
__device__ float g_W2d [HID * 2 * HID];
__device__ float g_W1Td[HID * 2 * HID];
__device__ float g_W2Td[HID * 2 * HID];

__global__ void prepW(const float* __restrict__ W1, const float* __restrict__ W2) {
    int idx = blockIdx.x * blockDim.x + threadIdx.x;
    if (idx < HID * HID) {
        int r = idx / HID, c = idx % HID;
        float w1 = W1[idx], w2 = W2[idx];
        g_W1d [r * 2 * HID + 2 * c] = w1;  g_W1d [r * 2 * HID + 2 * c + 1] = w1;
        g_W2d [r * 2 * HID + 2 * c] = w2;  g_W2d [r * 2 * HID + 2 * c + 1] = w2;
        g_W1Td[c * 2 * HID + 2 * r] = w1;  g_W1Td[c * 2 * HID + 2 * r + 1] = w1;
        g_W2Td[c * 2 * HID + 2 * r] = w2;  g_W2Td[c * 2 * HID + 2 * r + 1] = w2;
    }
}

typedef unsigned long long u64;
typedef unsigned int u32;

__device__ __forceinline__ u64 pack2(float lo, float hi) {
    u64 r; asm("mov.b64 %0, {%1, %2};" : "=l"(r) : "f"(lo), "f"(hi)); return r;
}
__device__ __forceinline__ float2 unpack2(u64 v) {
    float2 r; asm("mov.b64 {%0, %1}, %2;" : "=f"(r.x), "=f"(r.y) : "l"(v)); return r;
}
__device__ __forceinline__ u64 fma2(u64 a, u64 b, u64 c) {
    u64 d; asm("fma.rn.f32x2 %0, %1, %2, %3;" : "=l"(d) : "l"(a), "l"(b), "l"(c)); return d;
}

__device__ __forceinline__ float sigm(float x)     { return 1.0f / (1.0f + expf(-x)); }
__device__ __forceinline__ float softplusf(float x){ return fmaxf(x, 0.0f) + log1pf(expf(-fabsf(x))); }

__device__ __forceinline__ u32 bfpack(float a, float b) {
    __nv_bfloat162 p = __floats2bfloat162_rn(a, b);
    return *reinterpret_cast<u32*>(&p);
}
__device__ __forceinline__ float2 bfunpack(u32 v) {
    return __bfloat1622float2(*reinterpret_cast<__nv_bfloat162*>(&v));
}

// One k-step: C[r][c] += Apair_r * Wdup_c.  A pairs from LDS (sample-interleaved),
// W dup pairs from LDG buffer slot B. 36 FFMA2, 5 LDS, zero packs.
#define GEMM_STEP_B(kk, B)                                                      \
    {                                                                           \
        const float* ap = &db[(kk) * PADK + sp * SPS];                          \
        ulonglong2 A01 = *reinterpret_cast<const ulonglong2*>(ap);              \
        ulonglong2 A23 = *reinterpret_cast<const ulonglong2*>(ap + 4);          \
        ulonglong2 A45 = *reinterpret_cast<const ulonglong2*>(ap + 8);          \
        ulonglong2 A67 = *reinterpret_cast<const ulonglong2*>(ap + 12);         \
        u64 A8 = *reinterpret_cast<const u64*>(ap + 16);                        \
        u64 av[9] = {A01.x, A01.y, A23.x, A23.y, A45.x, A45.y, A67.x, A67.y, A8}; \
        u64 w0 = wb0[B].x, w1 = wb0[B].y, w2 = wb1[B].x, w3 = wb1[B].y;         \
        _Pragma("unroll")                                                       \
        for (int r = 0; r < 9; r++) {                                           \
            Cp[r][0] = fma2(av[r], w0, Cp[r][0]);                               \
            Cp[r][1] = fma2(av[r], w1, Cp[r][1]);                               \
            Cp[r][2] = fma2(av[r], w2, Cp[r][2]);                               \
            Cp[r][3] = fma2(av[r], w3, Cp[r][3]);                               \
        }                                                                       \
    }

// Full phase over duplicated W (row stride 2*HID), register double-buffered.
#define GEMM_PHASE(Wd)                                                          \
    {                                                                           \
        _Pragma("unroll")                                                       \
        for (int r = 0; r < 9; r++) {                                           \
            _Pragma("unroll")                                                   \
            for (int j = 0; j < 4; j++) Cp[r][j] = 0ull;                        \
        }                                                                       \
        const float* wp = &(Wd)[col0 * 2];                                      \
        ulonglong2 wb0[2], wb1[2];                                              \
        wb0[0] = *reinterpret_cast<const ulonglong2*>(wp);                      \
        wb1[0] = *reinterpret_cast<const ulonglong2*>(wp + 4);                  \
        for (int k = 0; k < HID - 2; k += 2) {                                  \
            wb0[1] = *reinterpret_cast<const ulonglong2*>(wp + 2 * HID);        \
            wb1[1] = *reinterpret_cast<const ulonglong2*>(wp + 2 * HID + 4);    \
            GEMM_STEP_B(k, 0);                                                  \
            wp += 4 * HID;                                                      \
            wb0[0] = *reinterpret_cast<const ulonglong2*>(wp);                  \
            wb1[0] = *reinterpret_cast<const ulonglong2*>(wp + 4);              \
            GEMM_STEP_B(k + 1, 1);                                              \
        }                                                                       \
        wb0[1] = *reinterpret_cast<const ulonglong2*>(wp + 2 * HID);            \
        wb1[1] = *reinterpret_cast<const ulonglong2*>(wp + 2 * HID + 4);        \
        GEMM_STEP_B(HID - 2, 0);                                                \
        GEMM_STEP_B(HID - 1, 1);                                                \
    }

__global__ void __launch_bounds__(NTH, 2) lnn_kernel(
    const float* __restrict__ z,
    const float* __restrict__ W0, const float* __restrict__ b0,
    const float* __restrict__ W1, const float* __restrict__ b1,
    const float* __restrict__ W2, const float* __restrict__ b2,
    const float* __restrict__ W3,
    float* __restrict__ out, int n)
{
    extern __shared__ float db[];              // [HID][PADK], sample-interleaved dirs
    __shared__ uint4 th2b[HID][SB];            // bf16-packed th2 per (col, sample)
    __shared__ float shz[SB][16];
    __shared__ float sh_g[SB][16];
    __shared__ float sh_H[SB][8][16];

    const int tid  = threadIdx.x;
    const int sp   = tid & 3;              // sample pair 0..3
    const int g    = tid >> 2;             // column group 0..49 (act)
    const int col0 = g * NCOL;
    const bool act = (g < NG);
    const int s0   = 2 * sp, s1v = 2 * sp + 1;
    const int base = blockIdx.x * SB;
    const int warp = tid >> 5, lane = tid & 31;

    for (int i = tid; i < SB * 16; i += NTH) {
        int smp = base + (i >> 4);
        if (smp >= n) smp = n - 1;
        shz[i >> 4][i & 15] = z[smp * 16 + (i & 15)];
    }
    __syncthreads();

    float s1r[2][NCOL], s2r[2][NCOL];
    u64 Cp[9][4];

    // ---------- phase 0: x1 = z@W0 + b0 ; seed tangents ----------
    if (act) {
        float xa0[NCOL], xa1[NCOL], bb[NCOL];
        *reinterpret_cast<float4*>(bb) = *reinterpret_cast<const float4*>(&b0[col0]);
        #pragma unroll
        for (int c = 0; c < NCOL; c++) { xa0[c] = bb[c]; xa1[c] = bb[c]; }
        #pragma unroll
        for (int m = 0; m < 16; m++) {
            float wv[NCOL];
            *reinterpret_cast<float4*>(wv) = *reinterpret_cast<const float4*>(&W0[m * HID + col0]);
            float z0 = shz[s0][m], z1 = shz[s1v][m];
            #pragma unroll
            for (int c = 0; c < NCOL; c++) {
                xa0[c] = fmaf(z0, wv[c], xa0[c]);
                xa1[c] = fmaf(z1, wv[c], xa1[c]);
            }
        }
        #pragma unroll
        for (int c = 0; c < NCOL; c++) {
            s1r[0][c] = sigm(xa0[c]);
            s1r[1][c] = sigm(xa1[c]);
            *reinterpret_cast<u64*>(&db[(col0 + c) * PADK + sp * SPS + 16]) =
                pack2(softplusf(xa0[c]), softplusf(xa1[c]));
        }
        #pragma unroll
        for (int d = 0; d < DD; d++) {
            float wv[NCOL];
            *reinterpret_cast<float4*>(wv) = *reinterpret_cast<const float4*>(&W0[(DD + d) * HID + col0]);
            #pragma unroll
            for (int c = 0; c < NCOL; c++)
                *reinterpret_cast<u64*>(&db[(col0 + c) * PADK + sp * SPS + 2 * d]) =
                    pack2(s1r[0][c] * wv[c], s1r[1][c] * wv[c]);
        }
    }
    __syncthreads();

    // ---------- phase 1: stream W1 -> x2 + t2 ----------
    if (act) { GEMM_PHASE(g_W1d); }
    __syncthreads();
    if (act) {
        float bb[NCOL];
        *reinterpret_cast<float4*>(bb) = *reinterpret_cast<const float4*>(&b1[col0]);
        #pragma unroll
        for (int c = 0; c < NCOL; c++) {
            float2 xp = unpack2(Cp[8][c]);
            float x0 = xp.x + bb[c], x1 = xp.y + bb[c];
            float sA = sigm(x0), sB = sigm(x1);
            s2r[0][c] = sA; s2r[1][c] = sB;
            float v0[DD], v1[DD];
            #pragma unroll
            for (int d = 0; d < DD; d++) {
                float2 t = unpack2(Cp[d][c]);
                v0[d] = sA * t.x; v1[d] = sB * t.y;       // th2 = s2*t2
            }
            float* p = &db[(col0 + c) * PADK + sp * SPS];
            *reinterpret_cast<float4*>(p)      = make_float4(v0[0], v1[0], v0[1], v1[1]);
            *reinterpret_cast<float4*>(p + 4)  = make_float4(v0[2], v1[2], v0[3], v1[3]);
            *reinterpret_cast<float4*>(p + 8)  = make_float4(v0[4], v1[4], v0[5], v1[5]);
            *reinterpret_cast<float4*>(p + 12) = make_float4(v0[6], v1[6], v0[7], v1[7]);
            *reinterpret_cast<u64*>(p + 16)    = pack2(softplusf(x0), softplusf(x1));   // h2
            uint4 t0, t1;
            t0.x = bfpack(v0[0], v0[1]); t0.y = bfpack(v0[2], v0[3]);
            t0.z = bfpack(v0[4], v0[5]); t0.w = bfpack(v0[6], v0[7]);
            t1.x = bfpack(v1[0], v1[1]); t1.y = bfpack(v1[2], v1[3]);
            t1.z = bfpack(v1[4], v1[5]); t1.w = bfpack(v1[6], v1[7]);
            th2b[col0 + c][s0]  = t0;
            th2b[col0 + c][s1v] = t1;
        }
    }
    __syncthreads();

    // ---------- phase 2: stream W2 -> x3 + t3 ----------
    if (act) { GEMM_PHASE(g_W2d); }
    __syncthreads();
    if (act) {
        float bb[NCOL], w3v[NCOL];
        *reinterpret_cast<float4*>(bb)  = *reinterpret_cast<const float4*>(&b2[col0]);
        *reinterpret_cast<float4*>(w3v) = *reinterpret_cast<const float4*>(&W3[col0]);
        #pragma unroll
        for (int c = 0; c < NCOL; c++) {
            float2 xp = unpack2(Cp[8][c]);
            float x0 = xp.x + bb[c], x1 = xp.y + bb[c];
            float sA = sigm(x0), sB = sigm(x1);
            float cA = w3v[c] * sA * (1.0f - sA);
            float cB = w3v[c] * sB * (1.0f - sB);
            float v0[DD], v1[DD];
            #pragma unroll
            for (int d = 0; d < DD; d++) {
                float2 t = unpack2(Cp[d][c]);
                v0[d] = cA * t.x; v1[d] = cB * t.y;       // delta-d3
            }
            float* p = &db[(col0 + c) * PADK + sp * SPS];
            *reinterpret_cast<float4*>(p)      = make_float4(v0[0], v1[0], v0[1], v1[1]);
            *reinterpret_cast<float4*>(p + 4)  = make_float4(v0[2], v1[2], v0[3], v1[3]);
            *reinterpret_cast<float4*>(p + 8)  = make_float4(v0[4], v1[4], v0[5], v1[5]);
            *reinterpret_cast<float4*>(p + 12) = make_float4(v0[6], v1[6], v0[7], v1[7]);
            *reinterpret_cast<u64*>(p + 16)    = pack2(w3v[c] * sA, w3v[c] * sB);      // d3
        }
    }
    __syncthreads();

    // ---------- phase 3: stream W2^T -> u2 + r2 ----------
    if (act) { GEMM_PHASE(g_W2Td); }
    __syncthreads();
    if (act) {
        #pragma unroll
        for (int c = 0; c < NCOL; c++) {
            float2 up = unpack2(Cp[8][c]);     // u2 (s0, s1)
            float sA = s2r[0][c], sB = s2r[1][c];
            float kA = (1.0f - sA) * up.x, kB = (1.0f - sB) * up.y;
            uint4 t0v = th2b[col0 + c][s0];
            uint4 t1v = th2b[col0 + c][s1v];
            float tA[DD], tB[DD];
            { float2 p2;
              p2 = bfunpack(t0v.x); tA[0] = p2.x; tA[1] = p2.y;
              p2 = bfunpack(t0v.y); tA[2] = p2.x; tA[3] = p2.y;
              p2 = bfunpack(t0v.z); tA[4] = p2.x; tA[5] = p2.y;
              p2 = bfunpack(t0v.w); tA[6] = p2.x; tA[7] = p2.y;
              p2 = bfunpack(t1v.x); tB[0] = p2.x; tB[1] = p2.y;
              p2 = bfunpack(t1v.y); tB[2] = p2.x; tB[3] = p2.y;
              p2 = bfunpack(t1v.z); tB[4] = p2.x; tB[5] = p2.y;
              p2 = bfunpack(t1v.w); tB[6] = p2.x; tB[7] = p2.y; }
            float v0[DD], v1[DD];
            #pragma unroll
            for (int d = 0; d < DD; d++) {
                float2 r = unpack2(Cp[d][c]);
                v0[d] = fmaf(sA, r.x, kA * tA[d]);        // delta-d2
                v1[d] = fmaf(sB, r.y, kB * tB[d]);
            }
            float* p = &db[(col0 + c) * PADK + sp * SPS];
            *reinterpret_cast<float4*>(p)      = make_float4(v0[0], v1[0], v0[1], v1[1]);
            *reinterpret_cast<float4*>(p + 4)  = make_float4(v0[2], v1[2], v0[3], v1[3]);
            *reinterpret_cast<float4*>(p + 8)  = make_float4(v0[4], v1[4], v0[5], v1[5]);
            *reinterpret_cast<float4*>(p + 12) = make_float4(v0[6], v1[6], v0[7], v1[7]);
            *reinterpret_cast<u64*>(p + 16)    = pack2(sA * up.x, sB * up.y);          // d2
        }
    }
    __syncthreads();

    // ---------- phase 4: stream W1^T -> u1 + r1 ----------
    if (act) { GEMM_PHASE(g_W1Td); }
    __syncthreads();
    if (act) {
        float coA[NCOL], coB[NCOL];
        #pragma unroll
        for (int c = 0; c < NCOL; c++) {
            float2 up = unpack2(Cp[8][c]);     // u1
            coA[c] = s1r[0][c] * (1.0f - s1r[0][c]) * up.x;
            coB[c] = s1r[1][c] * (1.0f - s1r[1][c]) * up.y;
            *reinterpret_cast<u64*>(&db[(col0 + c) * PADK + sp * SPS + 16]) =
                pack2(s1r[0][c] * up.x, s1r[1][c] * up.y);   // d1
        }
        #pragma unroll
        for (int d = 0; d < DD; d++) {
            float wv[NCOL];
            *reinterpret_cast<float4*>(wv) = *reinterpret_cast<const float4*>(&W0[(DD + d) * HID + col0]);
            #pragma unroll
            for (int c = 0; c < NCOL; c++) {
                float2 r = unpack2(Cp[d][c]);
                *reinterpret_cast<u64*>(&db[(col0 + c) * PADK + sp * SPS + 2 * d]) =
                    pack2(fmaf(s1r[0][c], r.x, coA[c] * wv[c]),
                          fmaf(s1r[1][c], r.y, coB[c] * wv[c]));   // delta-d1
            }
        }
    }
    __syncthreads();

    // ---------- final dots ----------
    for (int idx = warp; idx < SB * 16; idx += NW) {
        int ss = idx >> 4, m = idx & 15;
        float a = 0.0f;
        for (int k = lane; k < HID; k += 32)
            a = fmaf(W0[m * HID + k], db[k * PADK + (ss >> 1) * SPS + 16 + (ss & 1)], a);
        #pragma unroll
        for (int off = 16; off > 0; off >>= 1) a += __shfl_xor_sync(0xffffffffu, a, off);
        if (lane == 0) sh_g[ss][m] = a;
    }
    for (int idx = warp; idx < SB * 128; idx += NW) {
        int ss = idx >> 7;
        int r = idx & 127;
        int d = r >> 4, m = r & 15;
        float a = 0.0f;
        for (int k = lane; k < HID; k += 32)
            a = fmaf(W0[m * HID + k], db[k * PADK + (ss >> 1) * SPS + 2 * d + (ss & 1)], a);
        #pragma unroll
        for (int off = 16; off > 0; off >>= 1) a += __shfl_xor_sync(0xffffffffu, a, off);
        if (lane == 0) sh_H[ss][d][m] = a;
    }
    __syncthreads();

    // ---------- per-sample 8x8 solve + output ----------
    if (tid < SB && base + tid < n) {
        const int ss = tid;
        float Mt[DD][DD], Fv[DD], av2[DD], vv[DD];
        #pragma unroll
        for (int c = 0; c < DD; c++) vv[c] = shz[ss][DD + c];
        for (int r = 0; r < DD; r++)
            for (int c = 0; c < DD; c++)
                Mt[r][c] = sh_H[ss][r][DD + c] + ((r == c) ? 2.0f * EPSV : 0.0f);
        for (int p = 0; p < DD; p++) {
            float f = sh_g[ss][p];
            for (int c = 0; c < DD; c++) f -= sh_H[ss][p][c] * vv[c];
            Fv[p] = f;
        }
        for (int col = 0; col < DD; col++) {
            int piv = col; float best = fabsf(Mt[col][col]);
            for (int r = col + 1; r < DD; r++) {
                float m = fabsf(Mt[r][col]);
                if (m > best) { best = m; piv = r; }
            }
            if (piv != col) {
                for (int c = col; c < DD; c++) { float t = Mt[col][c]; Mt[col][c] = Mt[piv][c]; Mt[piv][c] = t; }
                float t = Fv[col]; Fv[col] = Fv[piv]; Fv[piv] = t;
            }
            float inv = 1.0f / Mt[col][col];
            for (int r = col + 1; r < DD; r++) {
                float fac = Mt[r][col] * inv;
                for (int c = col; c < DD; c++) Mt[r][c] -= fac * Mt[col][c];
                Fv[r] -= fac * Fv[col];
            }
        }
        for (int r = DD - 1; r >= 0; r--) {
            float x = Fv[r];
            for (int c = r + 1; c < DD; c++) x -= Mt[r][c] * av2[c];
            av2[r] = x / Mt[r][r];
        }
        const int gi = (base + ss) * 16;
        #pragma unroll
        for (int j = 0; j < DD; j++) out[gi + j] = vv[j];
        #pragma unroll
        for (int j = 0; j < DD; j++) out[gi + DD + j] = av2[j];
    }
}

extern "C" void kernel_launch(void* const* d_in, const int* in_sizes, int n_in,
                              void* d_out, int out_size) {
    const float* z  = (const float*)d_in[1];
    const float* W0 = (const float*)d_in[2];
    const float* b0 = (const float*)d_in[3];
    const float* W1 = (const float*)d_in[4];
    const float* b1 = (const float*)d_in[5];
    const float* W2 = (const float*)d_in[6];
    const float* b2 = (const float*)d_in[7];
    const float* W3 = (const float*)d_in[8];
    float* out = (float*)d_out;

    const int n = in_sizes[1] / 16;

    cudaFuncSetAttribute(lnn_kernel, cudaFuncAttributeMaxDynamicSharedMemorySize, DSMEM);

    prepW<<<(HID * HID + 255) / 256, 256>>>(W1, W2);

    const int blocks = (n + SB - 1) / SB;
    lnn_kernel<<<blocks, NTH, DSMEM>>>(z, W0, b0, W1, b1, W2, b2, W3, out, n);
}